// round 1
// baseline (speedup 1.0000x reference)
#include <cuda_runtime.h>
#include <cuda_bf16.h>
#include <cstdint>

// Problem constants
#define Bb   32
#define Ll   1024
#define Hh   512
#define NEG_INF_V (-1e7f)

// Scratch: score matrix S[b, q, a]  (128 MB) + softmax stats
__device__ float g_S[(size_t)Bb * Ll * Ll];
__device__ float g_rowmax[Bb * Ll];
__device__ float g_rowsum[Bb * Ll];
__device__ float g_colmax[Bb * Ll];
__device__ float g_colsum[Bb * Ll];

// ---------------------------------------------------------------------------
// Kernel 1: S[b,q,a] = temp * dot(q[b,q,:], a[b,a,:]), masked -> -1e7
// NT GEMM, 64x64 tile, BK=16, 256 threads, 4x4 micro-tile
// ---------------------------------------------------------------------------
__global__ void __launch_bounds__(256) score_kernel(
    const float* __restrict__ q, const float* __restrict__ a,
    const int* __restrict__ qm, const int* __restrict__ am,
    const float* __restrict__ temp)
{
    __shared__ float Qs[16][68];
    __shared__ float As[16][68];

    const int b  = blockIdx.z;
    const int m0 = blockIdx.y * 64;   // q rows
    const int n0 = blockIdx.x * 64;   // a rows
    const int tid = threadIdx.x;
    const int tx = tid & 15, ty = tid >> 4;

    const float* qb = q + (size_t)b * Ll * Hh;
    const float* ab = a + (size_t)b * Ll * Hh;

    float acc[4][4] = {};

    for (int k0 = 0; k0 < Hh; k0 += 16) {
        #pragma unroll
        for (int i = tid; i < 64 * 16; i += 256) {
            int r = i >> 4, c = i & 15;
            Qs[c][r] = qb[(size_t)(m0 + r) * Hh + k0 + c];
            As[c][r] = ab[(size_t)(n0 + r) * Hh + k0 + c];
        }
        __syncthreads();
        #pragma unroll
        for (int kk = 0; kk < 16; kk++) {
            float aq[4], av[4];
            #pragma unroll
            for (int i = 0; i < 4; i++) aq[i] = Qs[kk][ty * 4 + i];
            #pragma unroll
            for (int j = 0; j < 4; j++) av[j] = As[kk][tx * 4 + j];
            #pragma unroll
            for (int i = 0; i < 4; i++)
                #pragma unroll
                for (int j = 0; j < 4; j++)
                    acc[i][j] += aq[i] * av[j];
        }
        __syncthreads();
    }

    const float t = *temp;
    float* Sb = g_S + (size_t)b * Ll * Ll;

    int qmv[4], amv[4];
    #pragma unroll
    for (int i = 0; i < 4; i++) qmv[i] = qm[b * Ll + m0 + ty * 4 + i];
    #pragma unroll
    for (int j = 0; j < 4; j++) amv[j] = am[b * Ll + n0 + tx * 4 + j];

    #pragma unroll
    for (int i = 0; i < 4; i++) {
        int m = m0 + ty * 4 + i;
        #pragma unroll
        for (int j = 0; j < 4; j++) {
            int n = n0 + tx * 4 + j;
            float v = (qmv[i] != 0 && amv[j] != 0) ? acc[i][j] * t : NEG_INF_V;
            Sb[(size_t)m * Ll + n] = v;
        }
    }
}

// ---------------------------------------------------------------------------
// Kernel 2: per-row (over a, axis=2) max & sum(exp)
// one block (128 thr) per row; row kept in registers (8 vals/thread)
// ---------------------------------------------------------------------------
__global__ void __launch_bounds__(128) rowstats_kernel()
{
    const int row = blockIdx.x;                 // b*L + q
    const float* Sr = g_S + (size_t)row * Ll;
    const int tid = threadIdx.x;

    float v[8];
    float m = -3.4e38f;
    #pragma unroll
    for (int i = 0; i < 8; i++) { v[i] = Sr[i * 128 + tid]; m = fmaxf(m, v[i]); }

    #pragma unroll
    for (int o = 16; o; o >>= 1) m = fmaxf(m, __shfl_xor_sync(0xffffffffu, m, o));
    __shared__ float smx[4];
    if ((tid & 31) == 0) smx[tid >> 5] = m;
    __syncthreads();
    m = fmaxf(fmaxf(smx[0], smx[1]), fmaxf(smx[2], smx[3]));

    float s = 0.f;
    #pragma unroll
    for (int i = 0; i < 8; i++) s += __expf(v[i] - m);
    #pragma unroll
    for (int o = 16; o; o >>= 1) s += __shfl_xor_sync(0xffffffffu, s, o);
    __shared__ float ssm[4];
    if ((tid & 31) == 0) ssm[tid >> 5] = s;
    __syncthreads();
    if (tid == 0) {
        g_rowmax[row] = m;
        g_rowsum[row] = ssm[0] + ssm[1] + ssm[2] + ssm[3];
    }
}

// ---------------------------------------------------------------------------
// Kernel 3: per-column (over q, axis=1) max & sum(exp); thread per column,
// coalesced across columns, 8x unrolled for MLP
// ---------------------------------------------------------------------------
__global__ void __launch_bounds__(256) colstats_kernel()
{
    const int col = blockIdx.x * 256 + threadIdx.x;
    const int b   = blockIdx.y;
    const float* Sb = g_S + (size_t)b * Ll * Ll;

    float m = -3.4e38f;
    for (int qi = 0; qi < Ll; qi += 8) {
        float vv[8];
        #pragma unroll
        for (int u = 0; u < 8; u++) vv[u] = Sb[(size_t)(qi + u) * Ll + col];
        #pragma unroll
        for (int u = 0; u < 8; u++) m = fmaxf(m, vv[u]);
    }
    float s = 0.f;
    for (int qi = 0; qi < Ll; qi += 8) {
        float vv[8];
        #pragma unroll
        for (int u = 0; u < 8; u++) vv[u] = Sb[(size_t)(qi + u) * Ll + col];
        #pragma unroll
        for (int u = 0; u < 8; u++) s += __expf(vv[u] - m);
    }
    g_colmax[b * Ll + col] = m;
    g_colsum[b * Ll + col] = s;
}

// ---------------------------------------------------------------------------
// Kernel 4: q_s[b,q,h] = (1/rowsum[q]) * sum_a exp(S[q,a]-rowmax[q]) * a[b,a,h]
// M=q(1024), N=h(512), K=a(1024); exp fused into smem load; writes out1 upper
// ---------------------------------------------------------------------------
__global__ void __launch_bounds__(256) gemmQ_kernel(
    const float* __restrict__ amat, float* __restrict__ out)
{
    __shared__ float Ps[16][68];
    __shared__ float Bs[16][68];
    __shared__ float rm[64];

    const int b  = blockIdx.z;
    const int m0 = blockIdx.y * 64;   // q
    const int n0 = blockIdx.x * 64;   // h
    const int tid = threadIdx.x;
    const int tx = tid & 15, ty = tid >> 4;

    const float* Sb = g_S + (size_t)b * Ll * Ll;
    const float* ab = amat + (size_t)b * Ll * Hh;

    if (tid < 64) rm[tid] = g_rowmax[b * Ll + m0 + tid];
    __syncthreads();

    float acc[4][4] = {};

    for (int k0 = 0; k0 < Ll; k0 += 16) {
        #pragma unroll
        for (int i = tid; i < 64 * 16; i += 256) {
            int r = i >> 4, c = i & 15;
            Ps[c][r] = __expf(Sb[(size_t)(m0 + r) * Ll + k0 + c] - rm[r]);
        }
        #pragma unroll
        for (int i = tid; i < 16 * 64; i += 256) {
            int r = i >> 6, c = i & 63;
            Bs[r][c] = ab[(size_t)(k0 + r) * Hh + n0 + c];
        }
        __syncthreads();
        #pragma unroll
        for (int kk = 0; kk < 16; kk++) {
            float ap[4], bv[4];
            #pragma unroll
            for (int i = 0; i < 4; i++) ap[i] = Ps[kk][ty * 4 + i];
            #pragma unroll
            for (int j = 0; j < 4; j++) bv[j] = Bs[kk][tx * 4 + j];
            #pragma unroll
            for (int i = 0; i < 4; i++)
                #pragma unroll
                for (int j = 0; j < 4; j++)
                    acc[i][j] += ap[i] * bv[j];
        }
        __syncthreads();
    }

    #pragma unroll
    for (int i = 0; i < 4; i++) {
        int m = m0 + ty * 4 + i;
        float inv = 1.f / g_rowsum[b * Ll + m];
        #pragma unroll
        for (int j = 0; j < 4; j++) {
            int n = n0 + tx * 4 + j;
            out[((size_t)b * Ll + m) * 1024 + 512 + n] = acc[i][j] * inv;
        }
    }
}

// ---------------------------------------------------------------------------
// Kernel 5: a_s[b,a,h] = (1/colsum[a]) * sum_q exp(S[q,a]-colmax[a]) * q[b,q,h]
// M=a(1024), N=h(512), K=q(1024); S read transposed; writes out2 upper
// ---------------------------------------------------------------------------
__global__ void __launch_bounds__(256) gemmA_kernel(
    const float* __restrict__ qmat, float* __restrict__ out)
{
    __shared__ float As_[16][68];
    __shared__ float Bs[16][68];
    __shared__ float cm[64];

    const int b  = blockIdx.z;
    const int m0 = blockIdx.y * 64;   // a index
    const int n0 = blockIdx.x * 64;   // h
    const int tid = threadIdx.x;
    const int tx = tid & 15, ty = tid >> 4;

    const float* Sb = g_S + (size_t)b * Ll * Ll;
    const float* qb = qmat + (size_t)b * Ll * Hh;

    if (tid < 64) cm[tid] = g_colmax[b * Ll + m0 + tid];
    __syncthreads();

    float acc[4][4] = {};

    for (int k0 = 0; k0 < Ll; k0 += 16) {
        #pragma unroll
        for (int i = tid; i < 16 * 64; i += 256) {
            int r = i >> 6, c = i & 63;   // r = k (q row), c = m (a col)
            As_[r][c] = __expf(Sb[(size_t)(k0 + r) * Ll + m0 + c] - cm[c]);
        }
        #pragma unroll
        for (int i = tid; i < 16 * 64; i += 256) {
            int r = i >> 6, c = i & 63;
            Bs[r][c] = qb[(size_t)(k0 + r) * Hh + n0 + c];
        }
        __syncthreads();
        #pragma unroll
        for (int kk = 0; kk < 16; kk++) {
            float ap[4], bv[4];
            #pragma unroll
            for (int i = 0; i < 4; i++) ap[i] = As_[kk][ty * 4 + i];
            #pragma unroll
            for (int j = 0; j < 4; j++) bv[j] = Bs[kk][tx * 4 + j];
            #pragma unroll
            for (int i = 0; i < 4; i++)
                #pragma unroll
                for (int j = 0; j < 4; j++)
                    acc[i][j] += ap[i] * bv[j];
        }
        __syncthreads();
    }

    const size_t OUT2 = (size_t)Bb * Ll * 1024;   // second output tensor offset
    #pragma unroll
    for (int i = 0; i < 4; i++) {
        int m = m0 + ty * 4 + i;
        float inv = 1.f / g_colsum[b * Ll + m];
        #pragma unroll
        for (int j = 0; j < 4; j++) {
            int n = n0 + tx * 4 + j;
            out[OUT2 + ((size_t)b * Ll + m) * 1024 + 512 + n] = acc[i][j] * inv;
        }
    }
}

// ---------------------------------------------------------------------------
// Kernel 6: copy q -> out1[:, :, 0:512] and a -> out2[:, :, 0:512] (float4)
// ---------------------------------------------------------------------------
__global__ void __launch_bounds__(256) copy_kernel(
    const float4* __restrict__ q4, const float4* __restrict__ a4,
    float4* __restrict__ out4)
{
    size_t i = (size_t)blockIdx.x * blockDim.x + threadIdx.x;   // < 4M
    size_t row = i >> 7;           // (b*L + l)
    size_t c   = i & 127;          // h/4 in [0,128)
    size_t o   = row * 256 + c;    // out row stride = 1024 floats = 256 float4
    out4[o] = q4[i];
    out4[(size_t)8388608 + o] = a4[i];   // OUT2 offset in float4 units
}

// ---------------------------------------------------------------------------
extern "C" void kernel_launch(void* const* d_in, const int* in_sizes, int n_in,
                              void* d_out, int out_size)
{
    const float* q    = (const float*)d_in[0];
    const float* a    = (const float*)d_in[1];
    const int*   qm   = (const int*)  d_in[2];
    const int*   am   = (const int*)  d_in[3];
    const float* temp = (const float*)d_in[4];
    float* out = (float*)d_out;

    // 1. masked scaled scores into g_S
    score_kernel<<<dim3(16, 16, 32), 256>>>(q, a, qm, am, temp);
    // 2. softmax stats, both axes
    rowstats_kernel<<<Bb * Ll, 128>>>();
    colstats_kernel<<<dim3(4, 32), 256>>>();
    // 3. aggregation GEMMs with fused exp + deferred normalization
    gemmQ_kernel<<<dim3(8, 16, 32), 256>>>(a, out);
    gemmA_kernel<<<dim3(8, 16, 32), 256>>>(q, out);
    // 4. raw copies into lower halves
    copy_kernel<<<16384, 256>>>((const float4*)q, (const float4*)a, (float4*)out);
}

// round 3
// speedup vs baseline: 2.8906x; 2.8906x over previous
#include <cuda_runtime.h>
#include <cuda_bf16.h>
#include <cstdint>

#define Bb 32
#define Ll 1024
#define Hh 512
#define NEG_INF_V (-1e7f)

// Scratch: score matrix S[b,q,a] (fp32, 128 MB) + softmax stats
__device__ float g_S[(size_t)Bb * Ll * Ll];
__device__ float g_rowmax[Bb * Ll];
__device__ float g_rowsum[Bb * Ll];
__device__ float g_colmax[Bb * Ll];
__device__ float g_colsum[Bb * Ll];

// ---------------------------------------------------------------------------
// helpers
// ---------------------------------------------------------------------------
__device__ __forceinline__ uint32_t s2u(const void* p) {
    uint32_t a;
    asm("{ .reg .u64 t; cvta.to.shared.u64 t, %1; cvt.u32.u64 %0, t; }" : "=r"(a) : "l"(p));
    return a;
}

#define LDSM_X4(r0, r1, r2, r3, addr)                                        \
    asm volatile("ldmatrix.sync.aligned.m8n8.x4.shared.b16 {%0,%1,%2,%3}, [%4];" \
                 : "=r"(r0), "=r"(r1), "=r"(r2), "=r"(r3) : "r"(addr))
#define LDSM_X2(r0, r1, addr)                                                \
    asm volatile("ldmatrix.sync.aligned.m8n8.x2.shared.b16 {%0,%1}, [%2];"   \
                 : "=r"(r0), "=r"(r1) : "r"(addr))

#define MMA_BF16(c, a, b)                                                    \
    asm volatile("mma.sync.aligned.m16n8k16.row.col.f32.bf16.bf16.f32 "      \
                 "{%0,%1,%2,%3}, {%4,%5,%6,%7}, {%8,%9}, {%0,%1,%2,%3};"     \
                 : "+f"((c)[0]), "+f"((c)[1]), "+f"((c)[2]), "+f"((c)[3])    \
                 : "r"((a)[0]), "r"((a)[1]), "r"((a)[2]), "r"((a)[3]),       \
                   "r"((b)[0]), "r"((b)[1]))

// fp32 -> bf16 hi + bf16 lo split (pairwise, packed)
__device__ __forceinline__ void split2(float x0, float x1, uint32_t& h, uint32_t& l) {
    __nv_bfloat162 hb = __floats2bfloat162_rn(x0, x1);
    float r0 = x0 - __low2float(hb);
    float r1 = x1 - __high2float(hb);
    __nv_bfloat162 lb = __floats2bfloat162_rn(r0, r1);
    h = reinterpret_cast<uint32_t&>(hb);
    l = reinterpret_cast<uint32_t&>(lb);
}

// smem tile geometry: [128 rows][64 k] bf16, pitch 72 halves (144 B)
#define LDP 72
#define TILE_B 18432          // 128 * 72 * 2

// ---- K-major loader: dest[row][k] = src[row*ld + k0 + k] ----
__device__ __forceinline__ void ld_km(char* hi, char* lo,
    const float* __restrict__ src, int ld, int k0, int tid)
{
#pragma unroll
    for (int i = 0; i < 8; i++) {
        int idx = (i << 8) + tid;
        int row = idx >> 4, c4 = idx & 15;
        const float4 x = *reinterpret_cast<const float4*>(src + (size_t)row * ld + k0 + (c4 << 2));
        uint32_t h01, l01, h23, l23;
        split2(x.x, x.y, h01, l01);
        split2(x.z, x.w, h23, l23);
        uint32_t off = (uint32_t)(row * LDP + (c4 << 2)) * 2;
        *reinterpret_cast<uint2*>(hi + off) = make_uint2(h01, h23);
        *reinterpret_cast<uint2*>(lo + off) = make_uint2(l01, l23);
    }
}

// ---- K-major loader with exp(x - bias[row]) fused ----
__device__ __forceinline__ void ld_km_exp(char* hi, char* lo,
    const float* __restrict__ src, int ld, int k0, const float* __restrict__ bias, int tid)
{
#pragma unroll
    for (int i = 0; i < 8; i++) {
        int idx = (i << 8) + tid;
        int row = idx >> 4, c4 = idx & 15;
        float4 x = *reinterpret_cast<const float4*>(src + (size_t)row * ld + k0 + (c4 << 2));
        float bm = bias[row];
        x.x = __expf(x.x - bm); x.y = __expf(x.y - bm);
        x.z = __expf(x.z - bm); x.w = __expf(x.w - bm);
        uint32_t h01, l01, h23, l23;
        split2(x.x, x.y, h01, l01);
        split2(x.z, x.w, h23, l23);
        uint32_t off = (uint32_t)(row * LDP + (c4 << 2)) * 2;
        *reinterpret_cast<uint2*>(hi + off) = make_uint2(h01, h23);
        *reinterpret_cast<uint2*>(lo + off) = make_uint2(l01, l23);
    }
}

// ---- transposed loader: dest[n][k] = src[k*ld + n]  (n fast in gmem) ----
__device__ __forceinline__ void ld_tr(char* hi, char* lo,
    const float* __restrict__ src, int ld, int tid)
{
#pragma unroll
    for (int i = 0; i < 8; i++) {
        int idx = (i << 8) + tid;
        int n = idx & 127, k4 = idx >> 7;       // k4 in [0,16)
        const float* s0 = src + (size_t)(k4 << 2) * ld + n;
        float x0 = s0[0];
        float x1 = s0[ld];
        float x2 = s0[2 * (size_t)ld];
        float x3 = s0[3 * (size_t)ld];
        uint32_t h01, l01, h23, l23;
        split2(x0, x1, h01, l01);
        split2(x2, x3, h23, l23);
        uint32_t off = (uint32_t)(n * LDP + (k4 << 2)) * 2;
        *reinterpret_cast<uint2*>(hi + off) = make_uint2(h01, h23);
        *reinterpret_cast<uint2*>(lo + off) = make_uint2(l01, l23);
    }
}

// ---- transposed loader with exp(x - bias[n]) fused ----
__device__ __forceinline__ void ld_tr_exp(char* hi, char* lo,
    const float* __restrict__ src, int ld, const float* __restrict__ bias, int tid)
{
#pragma unroll
    for (int i = 0; i < 8; i++) {
        int idx = (i << 8) + tid;
        int n = idx & 127, k4 = idx >> 7;
        const float* s0 = src + (size_t)(k4 << 2) * ld + n;
        float bm = bias[n];
        float x0 = __expf(s0[0] - bm);
        float x1 = __expf(s0[ld] - bm);
        float x2 = __expf(s0[2 * (size_t)ld] - bm);
        float x3 = __expf(s0[3 * (size_t)ld] - bm);
        uint32_t h01, l01, h23, l23;
        split2(x0, x1, h01, l01);
        split2(x2, x3, h23, l23);
        uint32_t off = (uint32_t)(n * LDP + (k4 << 2)) * 2;
        *reinterpret_cast<uint2*>(hi + off) = make_uint2(h01, h23);
        *reinterpret_cast<uint2*>(lo + off) = make_uint2(l01, l23);
    }
}

// ---- per-warp mainloop body: one 64-wide K chunk of compensated MMAs ----
// warp tile: 64 (M) x 32 (N); acc[4 mt][4 nt][4]
__device__ __forceinline__ void mma_chunk(float acc[4][4][4],
    uint32_t ah_b, uint32_t al_b, uint32_t bh_b, uint32_t bl_b,
    int wm, int wn, int lane)
{
    const int l16 = lane & 15, lk = lane >> 4;        // A frag addressing
    const int l8  = lane & 7,  lb = (lane >> 3) & 1;  // B frag addressing
#pragma unroll
    for (int ks = 0; ks < 4; ks++) {
        const int k0 = ks << 4;
        uint32_t bh[4][2], bl[4][2], af[4][4];
#pragma unroll
        for (int nt = 0; nt < 4; nt++) {
            uint32_t boff = (uint32_t)((wn + nt * 8 + l8) * LDP + k0 + lb * 8) * 2;
            LDSM_X2(bh[nt][0], bh[nt][1], bh_b + boff);
            LDSM_X2(bl[nt][0], bl[nt][1], bl_b + boff);
        }
#pragma unroll
        for (int mt = 0; mt < 4; mt++) {
            uint32_t aoff = (uint32_t)((wm + mt * 16 + l16) * LDP + k0 + lk * 8) * 2;
            LDSM_X4(af[mt][0], af[mt][1], af[mt][2], af[mt][3], ah_b + aoff);
        }
#pragma unroll
        for (int mt = 0; mt < 4; mt++)
#pragma unroll
            for (int nt = 0; nt < 4; nt++) {
                MMA_BF16(acc[mt][nt], af[mt], bh[nt]);
                MMA_BF16(acc[mt][nt], af[mt], bl[nt]);
            }
#pragma unroll
        for (int mt = 0; mt < 4; mt++) {
            uint32_t aoff = (uint32_t)((wm + mt * 16 + l16) * LDP + k0 + lk * 8) * 2;
            LDSM_X4(af[mt][0], af[mt][1], af[mt][2], af[mt][3], al_b + aoff);
        }
#pragma unroll
        for (int mt = 0; mt < 4; mt++)
#pragma unroll
            for (int nt = 0; nt < 4; nt++)
                MMA_BF16(acc[mt][nt], af[mt], bh[nt]);
    }
}

// ===========================================================================
// Kernel 1: S = mask(temp * q a^T)  — bf16x3 mma.sync, tile 128x128, K=512
// ===========================================================================
__global__ void __launch_bounds__(256, 2) score_tc(
    const float* __restrict__ q, const float* __restrict__ a,
    const int* __restrict__ qm, const int* __restrict__ am,
    const float* __restrict__ temp)
{
    extern __shared__ char sm[];
    __shared__ int s_qm[128], s_am[128];

    const int tid = threadIdx.x, lane = tid & 31, wid = tid >> 5;
    const int wm = (wid & 1) * 64, wn = (wid >> 1) * 32;
    const int b = blockIdx.z, m0 = blockIdx.y << 7, n0 = blockIdx.x << 7;

    char *ah = sm, *al = sm + TILE_B, *bh = sm + 2 * TILE_B, *bl = sm + 3 * TILE_B;
    uint32_t ah_b = s2u(ah), al_b = s2u(al), bh_b = s2u(bh), bl_b = s2u(bl);

    if (tid < 128) { s_qm[tid] = qm[b * Ll + m0 + tid]; s_am[tid] = am[b * Ll + n0 + tid]; }

    const float* qb = q + ((size_t)b * Ll + m0) * Hh;
    const float* ab = a + ((size_t)b * Ll + n0) * Hh;

    float acc[4][4][4] = {};
    for (int kc = 0; kc < 8; kc++) {
        int k0 = kc << 6;
        __syncthreads();
        ld_km(ah, al, qb, Hh, k0, tid);
        ld_km(bh, bl, ab, Hh, k0, tid);
        __syncthreads();
        mma_chunk(acc, ah_b, al_b, bh_b, bl_b, wm, wn, lane);
    }

    const float t = *temp;
#pragma unroll
    for (int mt = 0; mt < 4; mt++)
#pragma unroll
        for (int h2 = 0; h2 < 2; h2++) {
            int mloc = wm + mt * 16 + (lane >> 2) + h2 * 8;
            int qv = s_qm[mloc];
            float* row = g_S + ((size_t)b * Ll + m0 + mloc) * Ll + n0 + wn + (lane & 3) * 2;
#pragma unroll
            for (int nt = 0; nt < 4; nt++) {
                int c = wn + nt * 8 + (lane & 3) * 2;
                float2 v;
                v.x = (qv && s_am[c])     ? acc[mt][nt][h2 * 2]     * t : NEG_INF_V;
                v.y = (qv && s_am[c + 1]) ? acc[mt][nt][h2 * 2 + 1] * t : NEG_INF_V;
                *reinterpret_cast<float2*>(row + nt * 8) = v;
            }
        }
}

// ===========================================================================
// Kernel 2/3: softmax stats over both axes
// ===========================================================================
__global__ void __launch_bounds__(128) rowstats_kernel()
{
    const int row = blockIdx.x;
    const float* Sr = g_S + (size_t)row * Ll;
    const int tid = threadIdx.x;

    float v[8];
    float m = -3.4e38f;
#pragma unroll
    for (int i = 0; i < 8; i++) { v[i] = Sr[i * 128 + tid]; m = fmaxf(m, v[i]); }
#pragma unroll
    for (int o = 16; o; o >>= 1) m = fmaxf(m, __shfl_xor_sync(0xffffffffu, m, o));
    __shared__ float smx[4];
    if ((tid & 31) == 0) smx[tid >> 5] = m;
    __syncthreads();
    m = fmaxf(fmaxf(smx[0], smx[1]), fmaxf(smx[2], smx[3]));

    float s = 0.f;
#pragma unroll
    for (int i = 0; i < 8; i++) s += __expf(v[i] - m);
#pragma unroll
    for (int o = 16; o; o >>= 1) s += __shfl_xor_sync(0xffffffffu, s, o);
    __shared__ float ssm[4];
    if ((tid & 31) == 0) ssm[tid >> 5] = s;
    __syncthreads();
    if (tid == 0) { g_rowmax[row] = m; g_rowsum[row] = ssm[0] + ssm[1] + ssm[2] + ssm[3]; }
}

__global__ void __launch_bounds__(256) colstats_kernel()
{
    const int col = blockIdx.x * 256 + threadIdx.x;
    const int b = blockIdx.y;
    const float* Sb = g_S + (size_t)b * Ll * Ll;

    float m = -3.4e38f;
    for (int qi = 0; qi < Ll; qi += 8) {
        float vv[8];
#pragma unroll
        for (int u = 0; u < 8; u++) vv[u] = Sb[(size_t)(qi + u) * Ll + col];
#pragma unroll
        for (int u = 0; u < 8; u++) m = fmaxf(m, vv[u]);
    }
    float s = 0.f;
    for (int qi = 0; qi < Ll; qi += 8) {
        float vv[8];
#pragma unroll
        for (int u = 0; u < 8; u++) vv[u] = Sb[(size_t)(qi + u) * Ll + col];
#pragma unroll
        for (int u = 0; u < 8; u++) s += __expf(vv[u] - m);
    }
    g_colmax[b * Ll + col] = m;
    g_colsum[b * Ll + col] = s;
}

// ===========================================================================
// Kernel 4: q_s = softmax_a(S) @ a  — M=q, N=h, K=a
// ===========================================================================
__global__ void __launch_bounds__(256, 2) gemmQ_tc(
    const float* __restrict__ amat, float* __restrict__ out)
{
    extern __shared__ char sm[];
    __shared__ float s_rm[128];

    const int tid = threadIdx.x, lane = tid & 31, wid = tid >> 5;
    const int wm = (wid & 1) * 64, wn = (wid >> 1) * 32;
    const int b = blockIdx.z, m0 = blockIdx.y << 7, n0 = blockIdx.x << 7;

    char *ah = sm, *al = sm + TILE_B, *bh = sm + 2 * TILE_B, *bl = sm + 3 * TILE_B;
    uint32_t ah_b = s2u(ah), al_b = s2u(al), bh_b = s2u(bh), bl_b = s2u(bl);

    if (tid < 128) s_rm[tid] = g_rowmax[b * Ll + m0 + tid];
    __syncthreads();

    const float* Sb = g_S + (size_t)b * Ll * Ll + (size_t)m0 * Ll;
    const float* ab = amat + (size_t)b * Ll * Hh;

    float acc[4][4][4] = {};
    for (int kc = 0; kc < 16; kc++) {
        int k0 = kc << 6;
        ld_km_exp(ah, al, Sb, Ll, k0, s_rm, tid);
        ld_tr(bh, bl, ab + (size_t)k0 * Hh + n0, Hh, tid);
        __syncthreads();
        mma_chunk(acc, ah_b, al_b, bh_b, bl_b, wm, wn, lane);
        __syncthreads();
    }

#pragma unroll
    for (int mt = 0; mt < 4; mt++)
#pragma unroll
        for (int h2 = 0; h2 < 2; h2++) {
            int mloc = wm + mt * 16 + (lane >> 2) + h2 * 8;
            int m = m0 + mloc;
            float inv = 1.f / g_rowsum[b * Ll + m];
            float* row = out + ((size_t)b * Ll + m) * 1024 + 512 + n0 + wn + (lane & 3) * 2;
#pragma unroll
            for (int nt = 0; nt < 4; nt++) {
                float2 v;
                v.x = acc[mt][nt][h2 * 2] * inv;
                v.y = acc[mt][nt][h2 * 2 + 1] * inv;
                *reinterpret_cast<float2*>(row + nt * 8) = v;
            }
        }
}

// ===========================================================================
// Kernel 5: a_s = softmax_q(S)^T @ q  — M=a, N=h, K=q
// ===========================================================================
__global__ void __launch_bounds__(256, 2) gemmA_tc(
    const float* __restrict__ qmat, float* __restrict__ out)
{
    extern __shared__ char sm[];
    __shared__ float s_cm[128];

    const int tid = threadIdx.x, lane = tid & 31, wid = tid >> 5;
    const int wm = (wid & 1) * 64, wn = (wid >> 1) * 32;
    const int b = blockIdx.z, m0 = blockIdx.y << 7, n0 = blockIdx.x << 7;

    char *ah = sm, *al = sm + TILE_B, *bh = sm + 2 * TILE_B, *bl = sm + 3 * TILE_B;
    uint32_t ah_b = s2u(ah), al_b = s2u(al), bh_b = s2u(bh), bl_b = s2u(bl);

    if (tid < 128) s_cm[tid] = g_colmax[b * Ll + m0 + tid];
    __syncthreads();

    const float* Sb = g_S + (size_t)b * Ll * Ll;
    const float* qb = qmat + (size_t)b * Ll * Hh;

    float acc[4][4][4] = {};
    for (int kc = 0; kc < 16; kc++) {
        int k0 = kc << 6;
        ld_tr_exp(ah, al, Sb + (size_t)k0 * Ll + m0, Ll, s_cm, tid);
        ld_tr(bh, bl, qb + (size_t)k0 * Hh + n0, Hh, tid);
        __syncthreads();
        mma_chunk(acc, ah_b, al_b, bh_b, bl_b, wm, wn, lane);
        __syncthreads();
    }

    const size_t OUT2 = (size_t)Bb * Ll * 1024;
#pragma unroll
    for (int mt = 0; mt < 4; mt++)
#pragma unroll
        for (int h2 = 0; h2 < 2; h2++) {
            int mloc = wm + mt * 16 + (lane >> 2) + h2 * 8;
            int m = m0 + mloc;
            float inv = 1.f / g_colsum[b * Ll + m];
            float* row = out + OUT2 + ((size_t)b * Ll + m) * 1024 + 512 + n0 + wn + (lane & 3) * 2;
#pragma unroll
            for (int nt = 0; nt < 4; nt++) {
                float2 v;
                v.x = acc[mt][nt][h2 * 2] * inv;
                v.y = acc[mt][nt][h2 * 2 + 1] * inv;
                *reinterpret_cast<float2*>(row + nt * 8) = v;
            }
        }
}

// ===========================================================================
// Kernel 6: raw copies into the lower halves of both outputs
// ===========================================================================
__global__ void __launch_bounds__(256) copy_kernel(
    const float4* __restrict__ q4, const float4* __restrict__ a4,
    float4* __restrict__ out4)
{
    size_t i = (size_t)blockIdx.x * blockDim.x + threadIdx.x;   // < 4M
    size_t row = i >> 7;
    size_t c = i & 127;
    size_t o = row * 256 + c;
    out4[o] = q4[i];
    out4[(size_t)8388608 + o] = a4[i];
}

// ===========================================================================
extern "C" void kernel_launch(void* const* d_in, const int* in_sizes, int n_in,
                              void* d_out, int out_size)
{
    const float* q    = (const float*)d_in[0];
    const float* a    = (const float*)d_in[1];
    const int*   qm   = (const int*)  d_in[2];
    const int*   am   = (const int*)  d_in[3];
    const float* temp = (const float*)d_in[4];
    float* out = (float*)d_out;

    const int DSMEM = 4 * TILE_B;   // 73728 B
    cudaFuncSetAttribute(score_tc, cudaFuncAttributeMaxDynamicSharedMemorySize, DSMEM);
    cudaFuncSetAttribute(gemmQ_tc, cudaFuncAttributeMaxDynamicSharedMemorySize, DSMEM);
    cudaFuncSetAttribute(gemmA_tc, cudaFuncAttributeMaxDynamicSharedMemorySize, DSMEM);

    score_tc<<<dim3(8, 8, 32), 256, DSMEM>>>(q, a, qm, am, temp);
    rowstats_kernel<<<Bb * Ll, 128>>>();
    colstats_kernel<<<dim3(4, 32), 256>>>();
    gemmQ_tc<<<dim3(4, 8, 32), 256, DSMEM>>>(a, out);
    gemmA_tc<<<dim3(4, 8, 32), 256, DSMEM>>>(q, out);
    copy_kernel<<<16384, 256>>>((const float4*)q, (const float4*)a, (float4*)out);
}

// round 7
// speedup vs baseline: 2.9712x; 1.0279x over previous
#include <cuda_runtime.h>
#include <cuda_bf16.h>
#include <cstdint>

#define Bb 32
#define Ll 1024
#define Hh 512
#define NEG_INF_V (-1e7f)

// Scratch: score matrix S[b,q,a] (fp32, 128 MB) + softmax stats
__device__ float g_S[(size_t)Bb * Ll * Ll];
__device__ float g_rowmax[Bb * Ll];
__device__ float g_rowsum[Bb * Ll];
__device__ float g_colmax[Bb * Ll];
__device__ float g_colsum[Bb * Ll];

// ---------------------------------------------------------------------------
// helpers
// ---------------------------------------------------------------------------
__device__ __forceinline__ uint32_t s2u(const void* p) {
    uint32_t a;
    asm("{ .reg .u64 t; cvta.to.shared.u64 t, %1; cvt.u32.u64 %0, t; }" : "=r"(a) : "l"(p));
    return a;
}

#define LDSM_X4(r0, r1, r2, r3, addr)                                        \
    asm volatile("ldmatrix.sync.aligned.m8n8.x4.shared.b16 {%0,%1,%2,%3}, [%4];" \
                 : "=r"(r0), "=r"(r1), "=r"(r2), "=r"(r3) : "r"(addr))
#define LDSM_X2(r0, r1, addr)                                                \
    asm volatile("ldmatrix.sync.aligned.m8n8.x2.shared.b16 {%0,%1}, [%2];"   \
                 : "=r"(r0), "=r"(r1) : "r"(addr))

#define MMA_BF16(c, a, b)                                                    \
    asm volatile("mma.sync.aligned.m16n8k16.row.col.f32.bf16.bf16.f32 "      \
                 "{%0,%1,%2,%3}, {%4,%5,%6,%7}, {%8,%9}, {%0,%1,%2,%3};"     \
                 : "+f"((c)[0]), "+f"((c)[1]), "+f"((c)[2]), "+f"((c)[3])    \
                 : "r"((a)[0]), "r"((a)[1]), "r"((a)[2]), "r"((a)[3]),       \
                   "r"((b)[0]), "r"((b)[1]))

// fp32 -> bf16 hi + bf16 lo split (pairwise, packed)
__device__ __forceinline__ void split2(float x0, float x1, uint32_t& h, uint32_t& l) {
    __nv_bfloat162 hb = __floats2bfloat162_rn(x0, x1);
    float r0 = x0 - __low2float(hb);
    float r1 = x1 - __high2float(hb);
    __nv_bfloat162 lb = __floats2bfloat162_rn(r0, r1);
    h = reinterpret_cast<uint32_t&>(hb);
    l = reinterpret_cast<uint32_t&>(lb);
}

// smem tile geometry: [128 rows][64 k] bf16, pitch 72 halves (144 B)
#define LDP 72
#define TILE_B 18432            // 128 * 72 * 2
#define BUF_B (4 * TILE_B)      // ah, al, bh, bl

// ===== register-prefetch loaders (512 threads) =============================
// K-major tile: [128 rows][64 k] from src[row*ld + k0 + k]
__device__ __forceinline__ void ldg_km(float4 v[4],
    const float* __restrict__ src, int ld, int k0, int tid)
{
#pragma unroll
    for (int i = 0; i < 4; i++) {
        int idx = (i << 9) + tid;
        int row = idx >> 4, c4 = idx & 15;
        v[i] = *reinterpret_cast<const float4*>(src + (size_t)row * ld + k0 + (c4 << 2));
    }
}
__device__ __forceinline__ void st_km(const float4 v[4], char* hi, char* lo, int tid)
{
#pragma unroll
    for (int i = 0; i < 4; i++) {
        int idx = (i << 9) + tid;
        int row = idx >> 4, c4 = idx & 15;
        uint32_t h01, l01, h23, l23;
        split2(v[i].x, v[i].y, h01, l01);
        split2(v[i].z, v[i].w, h23, l23);
        uint32_t off = (uint32_t)(row * LDP + (c4 << 2)) * 2;
        *reinterpret_cast<uint2*>(hi + off) = make_uint2(h01, h23);
        *reinterpret_cast<uint2*>(lo + off) = make_uint2(l01, l23);
    }
}
__device__ __forceinline__ void st_km_exp(const float4 v[4], char* hi, char* lo,
    const float* __restrict__ bias, int tid)
{
#pragma unroll
    for (int i = 0; i < 4; i++) {
        int idx = (i << 9) + tid;
        int row = idx >> 4, c4 = idx & 15;
        float bm = bias[row];
        float x0 = __expf(v[i].x - bm), x1 = __expf(v[i].y - bm);
        float x2 = __expf(v[i].z - bm), x3 = __expf(v[i].w - bm);
        uint32_t h01, l01, h23, l23;
        split2(x0, x1, h01, l01);
        split2(x2, x3, h23, l23);
        uint32_t off = (uint32_t)(row * LDP + (c4 << 2)) * 2;
        *reinterpret_cast<uint2*>(hi + off) = make_uint2(h01, h23);
        *reinterpret_cast<uint2*>(lo + off) = make_uint2(l01, l23);
    }
}
// transposed tile: dest[n][k] = src[k*ld + n]  (n fast in gmem)
__device__ __forceinline__ void ldg_tr(float4 v[4],
    const float* __restrict__ src, int ld, int tid)
{
#pragma unroll
    for (int i = 0; i < 4; i++) {
        int idx = (i << 9) + tid;
        int n = idx & 127, k4 = idx >> 7;        // k4 in [0,16)
        const float* s0 = src + (size_t)(k4 << 2) * ld + n;
        v[i].x = s0[0];
        v[i].y = s0[ld];
        v[i].z = s0[2 * (size_t)ld];
        v[i].w = s0[3 * (size_t)ld];
    }
}
__device__ __forceinline__ void st_tr(const float4 v[4], char* hi, char* lo, int tid)
{
#pragma unroll
    for (int i = 0; i < 4; i++) {
        int idx = (i << 9) + tid;
        int n = idx & 127, k4 = idx >> 7;
        uint32_t h01, l01, h23, l23;
        split2(v[i].x, v[i].y, h01, l01);
        split2(v[i].z, v[i].w, h23, l23);
        uint32_t off = (uint32_t)(n * LDP + (k4 << 2)) * 2;
        *reinterpret_cast<uint2*>(hi + off) = make_uint2(h01, h23);
        *reinterpret_cast<uint2*>(lo + off) = make_uint2(l01, l23);
    }
}
__device__ __forceinline__ void st_tr_exp(const float4 v[4], char* hi, char* lo,
    const float* __restrict__ bias, int tid)
{
#pragma unroll
    for (int i = 0; i < 4; i++) {
        int idx = (i << 9) + tid;
        int n = idx & 127, k4 = idx >> 7;
        float bm = bias[n];
        float x0 = __expf(v[i].x - bm), x1 = __expf(v[i].y - bm);
        float x2 = __expf(v[i].z - bm), x3 = __expf(v[i].w - bm);
        uint32_t h01, l01, h23, l23;
        split2(x0, x1, h01, l01);
        split2(x2, x3, h23, l23);
        uint32_t off = (uint32_t)(n * LDP + (k4 << 2)) * 2;
        *reinterpret_cast<uint2*>(hi + off) = make_uint2(h01, h23);
        *reinterpret_cast<uint2*>(lo + off) = make_uint2(l01, l23);
    }
}

// ---- per-warp body: one 64-wide K chunk, warp tile 32(M) x 32(N) ----------
__device__ __forceinline__ void mma_chunk32(float acc[2][4][4],
    uint32_t ah_b, uint32_t al_b, uint32_t bh_b, uint32_t bl_b,
    int wm, int wn, int lane)
{
    const int l16 = lane & 15, lk = lane >> 4;
    const int l8 = lane & 7, lb = (lane >> 3) & 1;
#pragma unroll
    for (int ks = 0; ks < 4; ks++) {
        const int k0 = ks << 4;
        uint32_t bh[4][2], bl[4][2], af[2][4];
#pragma unroll
        for (int nt = 0; nt < 4; nt++) {
            uint32_t boff = (uint32_t)((wn + nt * 8 + l8) * LDP + k0 + lb * 8) * 2;
            LDSM_X2(bh[nt][0], bh[nt][1], bh_b + boff);
            LDSM_X2(bl[nt][0], bl[nt][1], bl_b + boff);
        }
#pragma unroll
        for (int mt = 0; mt < 2; mt++) {
            uint32_t aoff = (uint32_t)((wm + mt * 16 + l16) * LDP + k0 + lk * 8) * 2;
            LDSM_X4(af[mt][0], af[mt][1], af[mt][2], af[mt][3], ah_b + aoff);
        }
#pragma unroll
        for (int mt = 0; mt < 2; mt++)
#pragma unroll
            for (int nt = 0; nt < 4; nt++) {
                MMA_BF16(acc[mt][nt], af[mt], bh[nt]);
                MMA_BF16(acc[mt][nt], af[mt], bl[nt]);
            }
#pragma unroll
        for (int mt = 0; mt < 2; mt++) {
            uint32_t aoff = (uint32_t)((wm + mt * 16 + l16) * LDP + k0 + lk * 8) * 2;
            LDSM_X4(af[mt][0], af[mt][1], af[mt][2], af[mt][3], al_b + aoff);
        }
#pragma unroll
        for (int mt = 0; mt < 2; mt++)
#pragma unroll
            for (int nt = 0; nt < 4; nt++)
                MMA_BF16(acc[mt][nt], af[mt], bh[nt]);
    }
}

// ===========================================================================
// Kernel 1: S = mask(temp * q a^T) — pipelined, tile 128x128, K=512 (8 chunks)
// ===========================================================================
__global__ void __launch_bounds__(512, 1) score_tc(
    const float* __restrict__ q, const float* __restrict__ a,
    const int* __restrict__ qm, const int* __restrict__ am,
    const float* __restrict__ temp)
{
    extern __shared__ char sm[];
    __shared__ int s_qm[128], s_am[128];

    const int tid = threadIdx.x, lane = tid & 31, wid = tid >> 5;
    const int wm = (wid & 3) * 32, wn = (wid >> 2) * 32;
    const int b = blockIdx.z, m0 = blockIdx.y << 7, n0 = blockIdx.x << 7;

    if (tid < 128) { s_qm[tid] = qm[b * Ll + m0 + tid]; s_am[tid] = am[b * Ll + n0 + tid]; }

    const float* qb = q + ((size_t)b * Ll + m0) * Hh;
    const float* ab = a + ((size_t)b * Ll + n0) * Hh;

    float4 va[4], vb[4];
    ldg_km(va, qb, Hh, 0, tid);
    ldg_km(vb, ab, Hh, 0, tid);
    st_km(va, sm, sm + TILE_B, tid);
    st_km(vb, sm + 2 * TILE_B, sm + 3 * TILE_B, tid);
    __syncthreads();

    float acc[2][4][4] = {};
    for (int kc = 0; kc < 8; kc++) {
        int nk = kc + 1;
        if (nk < 8) {
            ldg_km(va, qb, Hh, nk << 6, tid);
            ldg_km(vb, ab, Hh, nk << 6, tid);
        }
        char* cur = sm + (kc & 1) * BUF_B;
        mma_chunk32(acc, s2u(cur), s2u(cur + TILE_B), s2u(cur + 2 * TILE_B),
                    s2u(cur + 3 * TILE_B), wm, wn, lane);
        if (nk < 8) {
            char* nb = sm + (nk & 1) * BUF_B;
            st_km(va, nb, nb + TILE_B, tid);
            st_km(vb, nb + 2 * TILE_B, nb + 3 * TILE_B, tid);
        }
        __syncthreads();
    }

    const float t = *temp;
#pragma unroll
    for (int mt = 0; mt < 2; mt++)
#pragma unroll
        for (int h2 = 0; h2 < 2; h2++) {
            int mloc = wm + mt * 16 + (lane >> 2) + h2 * 8;
            int qv = s_qm[mloc];
            float* row = g_S + ((size_t)b * Ll + m0 + mloc) * Ll + n0 + wn + (lane & 3) * 2;
#pragma unroll
            for (int nt = 0; nt < 4; nt++) {
                int c = wn + nt * 8 + (lane & 3) * 2;
                float2 v;
                v.x = (qv && s_am[c])     ? acc[mt][nt][h2 * 2]     * t : NEG_INF_V;
                v.y = (qv && s_am[c + 1]) ? acc[mt][nt][h2 * 2 + 1] * t : NEG_INF_V;
                *reinterpret_cast<float2*>(row + nt * 8) = v;
            }
        }
}

// ===========================================================================
// Kernel 2: per-row (axis=2) stats — coalesced, row in registers
// ===========================================================================
__global__ void __launch_bounds__(128) rowstats_kernel()
{
    const int row = blockIdx.x;
    const float* Sr = g_S + (size_t)row * Ll;
    const int tid = threadIdx.x;

    float v[8];
    float m = -3.4e38f;
#pragma unroll
    for (int i = 0; i < 8; i++) { v[i] = Sr[i * 128 + tid]; m = fmaxf(m, v[i]); }
#pragma unroll
    for (int o = 16; o; o >>= 1) m = fmaxf(m, __shfl_xor_sync(0xffffffffu, m, o));
    __shared__ float smx[4];
    if ((tid & 31) == 0) smx[tid >> 5] = m;
    __syncthreads();
    m = fmaxf(fmaxf(smx[0], smx[1]), fmaxf(smx[2], smx[3]));

    float s = 0.f;
#pragma unroll
    for (int i = 0; i < 8; i++) s += __expf(v[i] - m);
#pragma unroll
    for (int o = 16; o; o >>= 1) s += __shfl_xor_sync(0xffffffffu, s, o);
    __shared__ float ssm[4];
    if ((tid & 31) == 0) ssm[tid >> 5] = s;
    __syncthreads();
    if (tid == 0) { g_rowmax[row] = m; g_rowsum[row] = ssm[0] + ssm[1] + ssm[2] + ssm[3]; }
}

// ===========================================================================
// Kernel 3: per-column (axis=1) stats — float4 column groups, full sectors
// grid (8, 32); block 256 = 32 colgroups x 8 rowslices
// ===========================================================================
__global__ void __launch_bounds__(256) colstats_kernel()
{
    const int b = blockIdx.y;
    const int cg = threadIdx.x & 31;
    const int rs = threadIdx.x >> 5;
    const int c0 = blockIdx.x * 128 + cg * 4;
    const float* base = g_S + (size_t)b * Ll * Ll;
    __shared__ float4 red[256];

    float4 mx = make_float4(-3.4e38f, -3.4e38f, -3.4e38f, -3.4e38f);
    for (int r = rs * 128; r < rs * 128 + 128; r++) {
        float4 v = *reinterpret_cast<const float4*>(base + (size_t)r * Ll + c0);
        mx.x = fmaxf(mx.x, v.x); mx.y = fmaxf(mx.y, v.y);
        mx.z = fmaxf(mx.z, v.z); mx.w = fmaxf(mx.w, v.w);
    }
    red[threadIdx.x] = mx;
    __syncthreads();
    if (rs == 0) {
#pragma unroll
        for (int k = 1; k < 8; k++) {
            float4 o = red[k * 32 + cg];
            mx.x = fmaxf(mx.x, o.x); mx.y = fmaxf(mx.y, o.y);
            mx.z = fmaxf(mx.z, o.z); mx.w = fmaxf(mx.w, o.w);
        }
        red[cg] = mx;
    }
    __syncthreads();
    mx = red[cg];
    __syncthreads();

    float4 s4 = make_float4(0.f, 0.f, 0.f, 0.f);
    for (int r = rs * 128; r < rs * 128 + 128; r++) {
        float4 v = *reinterpret_cast<const float4*>(base + (size_t)r * Ll + c0);
        s4.x += __expf(v.x - mx.x); s4.y += __expf(v.y - mx.y);
        s4.z += __expf(v.z - mx.z); s4.w += __expf(v.w - mx.w);
    }
    red[threadIdx.x] = s4;
    __syncthreads();
    if (rs == 0) {
#pragma unroll
        for (int k = 1; k < 8; k++) {
            float4 o = red[k * 32 + cg];
            s4.x += o.x; s4.y += o.y; s4.z += o.z; s4.w += o.w;
        }
        *reinterpret_cast<float4*>(g_colmax + b * Ll + c0) = mx;
        *reinterpret_cast<float4*>(g_colsum + b * Ll + c0) = s4;
    }
}

// ===========================================================================
// Kernel 4: q_s = softmax_a(S) @ a — pipelined; M=q, N=h, K=a (16 chunks)
// ===========================================================================
__global__ void __launch_bounds__(512, 1) gemmQ_tc(
    const float* __restrict__ amat, float* __restrict__ out)
{
    extern __shared__ char sm[];
    __shared__ float s_rm[128];

    const int tid = threadIdx.x, lane = tid & 31, wid = tid >> 5;
    const int wm = (wid & 3) * 32, wn = (wid >> 2) * 32;
    const int b = blockIdx.z, m0 = blockIdx.y << 7, n0 = blockIdx.x << 7;

    if (tid < 128) s_rm[tid] = g_rowmax[b * Ll + m0 + tid];
    __syncthreads();

    const float* Sb = g_S + (size_t)b * Ll * Ll + (size_t)m0 * Ll;
    const float* ab = amat + (size_t)b * Ll * Hh;

    float4 va[4], vb[4];
    ldg_km(va, Sb, Ll, 0, tid);
    ldg_tr(vb, ab + n0, Hh, tid);
    st_km_exp(va, sm, sm + TILE_B, s_rm, tid);
    st_tr(vb, sm + 2 * TILE_B, sm + 3 * TILE_B, tid);
    __syncthreads();

    float acc[2][4][4] = {};
    for (int kc = 0; kc < 16; kc++) {
        int nk = kc + 1;
        if (nk < 16) {
            ldg_km(va, Sb, Ll, nk << 6, tid);
            ldg_tr(vb, ab + (size_t)(nk << 6) * Hh + n0, Hh, tid);
        }
        char* cur = sm + (kc & 1) * BUF_B;
        mma_chunk32(acc, s2u(cur), s2u(cur + TILE_B), s2u(cur + 2 * TILE_B),
                    s2u(cur + 3 * TILE_B), wm, wn, lane);
        if (nk < 16) {
            char* nb = sm + (nk & 1) * BUF_B;
            st_km_exp(va, nb, nb + TILE_B, s_rm, tid);
            st_tr(vb, nb + 2 * TILE_B, nb + 3 * TILE_B, tid);
        }
        __syncthreads();
    }

#pragma unroll
    for (int mt = 0; mt < 2; mt++)
#pragma unroll
        for (int h2 = 0; h2 < 2; h2++) {
            int mloc = wm + mt * 16 + (lane >> 2) + h2 * 8;
            int m = m0 + mloc;
            float inv = 1.f / g_rowsum[b * Ll + m];
            float* row = out + ((size_t)b * Ll + m) * 1024 + 512 + n0 + wn + (lane & 3) * 2;
#pragma unroll
            for (int nt = 0; nt < 4; nt++) {
                float2 v;
                v.x = acc[mt][nt][h2 * 2] * inv;
                v.y = acc[mt][nt][h2 * 2 + 1] * inv;
                *reinterpret_cast<float2*>(row + nt * 8) = v;
            }
        }
}

// ===========================================================================
// Kernel 5: a_s = softmax_q(S)^T @ q — pipelined; M=a, N=h, K=q (16 chunks)
// ===========================================================================
__global__ void __launch_bounds__(512, 1) gemmA_tc(
    const float* __restrict__ qmat, float* __restrict__ out)
{
    extern __shared__ char sm[];
    __shared__ float s_cm[128];

    const int tid = threadIdx.x, lane = tid & 31, wid = tid >> 5;
    const int wm = (wid & 3) * 32, wn = (wid >> 2) * 32;
    const int b = blockIdx.z, m0 = blockIdx.y << 7, n0 = blockIdx.x << 7;

    if (tid < 128) s_cm[tid] = g_colmax[b * Ll + m0 + tid];
    __syncthreads();

    const float* Sb = g_S + (size_t)b * Ll * Ll;
    const float* qb = qmat + (size_t)b * Ll * Hh;

    float4 va[4], vb[4];
    ldg_tr(va, Sb + m0, Ll, tid);
    ldg_tr(vb, qb + n0, Hh, tid);
    st_tr_exp(va, sm, sm + TILE_B, s_cm, tid);
    st_tr(vb, sm + 2 * TILE_B, sm + 3 * TILE_B, tid);
    __syncthreads();

    float acc[2][4][4] = {};
    for (int kc = 0; kc < 16; kc++) {
        int nk = kc + 1;
        if (nk < 16) {
            ldg_tr(va, Sb + (size_t)(nk << 6) * Ll + m0, Ll, tid);
            ldg_tr(vb, qb + (size_t)(nk << 6) * Hh + n0, Hh, tid);
        }
        char* cur = sm + (kc & 1) * BUF_B;
        mma_chunk32(acc, s2u(cur), s2u(cur + TILE_B), s2u(cur + 2 * TILE_B),
                    s2u(cur + 3 * TILE_B), wm, wn, lane);
        if (nk < 16) {
            char* nb = sm + (nk & 1) * BUF_B;
            st_tr_exp(va, nb, nb + TILE_B, s_cm, tid);
            st_tr(vb, nb + 2 * TILE_B, nb + 3 * TILE_B, tid);
        }
        __syncthreads();
    }

    const size_t OUT2 = (size_t)Bb * Ll * 1024;
#pragma unroll
    for (int mt = 0; mt < 2; mt++)
#pragma unroll
        for (int h2 = 0; h2 < 2; h2++) {
            int mloc = wm + mt * 16 + (lane >> 2) + h2 * 8;
            int m = m0 + mloc;
            float inv = 1.f / g_colsum[b * Ll + m];
            float* row = out + OUT2 + ((size_t)b * Ll + m) * 1024 + 512 + n0 + wn + (lane & 3) * 2;
#pragma unroll
            for (int nt = 0; nt < 4; nt++) {
                float2 v;
                v.x = acc[mt][nt][h2 * 2] * inv;
                v.y = acc[mt][nt][h2 * 2 + 1] * inv;
                *reinterpret_cast<float2*>(row + nt * 8) = v;
            }
        }
}

// ===========================================================================
// Kernel 6: raw copies into the lower halves of both outputs
// ===========================================================================
__global__ void __launch_bounds__(256) copy_kernel(
    const float4* __restrict__ q4, const float4* __restrict__ a4,
    float4* __restrict__ out4)
{
    size_t i = (size_t)blockIdx.x * blockDim.x + threadIdx.x;   // < 4M
    size_t row = i >> 7;
    size_t c = i & 127;
    size_t o = row * 256 + c;
    out4[o] = q4[i];
    out4[(size_t)8388608 + o] = a4[i];
}

// ===========================================================================
extern "C" void kernel_launch(void* const* d_in, const int* in_sizes, int n_in,
                              void* d_out, int out_size)
{
    const float* q    = (const float*)d_in[0];
    const float* a    = (const float*)d_in[1];
    const int*   qm   = (const int*)  d_in[2];
    const int*   am   = (const int*)  d_in[3];
    const float* temp = (const float*)d_in[4];
    float* out = (float*)d_out;

    const int DSMEM = 2 * BUF_B;   // 147456 B (double-buffered 4-tile set)
    cudaFuncSetAttribute(score_tc, cudaFuncAttributeMaxDynamicSharedMemorySize, DSMEM);
    cudaFuncSetAttribute(gemmQ_tc, cudaFuncAttributeMaxDynamicSharedMemorySize, DSMEM);
    cudaFuncSetAttribute(gemmA_tc, cudaFuncAttributeMaxDynamicSharedMemorySize, DSMEM);

    score_tc<<<dim3(8, 8, 32), 512, DSMEM>>>(q, a, qm, am, temp);
    rowstats_kernel<<<Bb * Ll, 128>>>();
    colstats_kernel<<<dim3(8, 32), 256>>>();
    gemmQ_tc<<<dim3(4, 8, 32), 512, DSMEM>>>(a, out);
    gemmA_tc<<<dim3(4, 8, 32), 512, DSMEM>>>(q, out);
    copy_kernel<<<16384, 256>>>((const float4*)q, (const float4*)a, (float4*)out);
}